// round 14
// baseline (speedup 1.0000x reference)
#include <cuda_runtime.h>
#include <cuda_fp16.h>

#define NN 2048
#define EE 65536
#define WORDS 64
#define NBMAX 2048
#define C_IN 128
#define H1D 3200
#define H2D 1600
#define ODIM 32
#define SK3 4

// ---------------- scratch (device globals) ----------------
__device__ unsigned g_adj[NN * WORDS];
__device__ unsigned g_rA [NN * WORDS];
__device__ unsigned g_rB [NN * WORDS];
__device__ int      g_nbr[(size_t)NN * NBMAX];
__device__ int      g_cnt[NN];
__device__ float    g_dvec[NN];
__device__ float    g_u  [NN * H2D];
__device__ float    g_va [NN * C_IN];
__device__ float    g_vb [NN * C_IN];
__device__ float    g_h2 [NN * H2D];
__device__ float    g_g3 [NN * ODIM];
__device__ float    g_g3p[SK3 * NN * ODIM];
// fp16 operands / iterates
__device__ __half g_vha[NN * H2D], g_vhb[NN * H2D];
__device__ __half g_zhi[NN * C_IN],  g_zlo[NN * C_IN];
__device__ __half g_w1h[C_IN * H1D];
__device__ __half g_w2h[H1D * H2D];
__device__ __half g_h1h[(size_t)NN * H1D];

// ---------------- utility kernels ----------------
__global__ void k_zero_u32(unsigned* p, int n) {
    int i = blockIdx.x * blockDim.x + threadIdx.x;
    if (i < n) p[i] = 0u;
}

__global__ void k_build_adj(const int* __restrict__ ei, unsigned* __restrict__ adj) {
    int e = blockIdx.x * blockDim.x + threadIdx.x;
    if (e < EE) {
        int src = ei[e];
        int dst = ei[EE + e];
        atomicOr(&adj[dst * WORDS + (src >> 5)], 1u << (src & 31));
    }
}

// Warp-per-row: build sorted neighbor list + write reach seed R = adj | diag.
__global__ __launch_bounds__(256)
void k_build_fused(const unsigned* __restrict__ adj,
                   int* __restrict__ nbr, int* __restrict__ cnt,
                   unsigned* __restrict__ R) {
    int warp = threadIdx.x >> 5;
    int lane = threadIdx.x & 31;
    int u = blockIdx.x * 8 + warp;
    const unsigned* row = adj + u * WORDS;
    unsigned w0 = row[lane];
    unsigned w1 = row[lane + 32];
    int dw = u >> 5;
    unsigned db = 1u << (u & 31);
    R[u * WORDS + lane]      = (dw == lane)      ? (w0 | db) : w0;
    R[u * WORDS + lane + 32] = (dw == lane + 32) ? (w1 | db) : w1;

    int c0 = __popc(w0), c1 = __popc(w1);
    int s0 = c0, s1 = c1;
    #pragma unroll
    for (int off = 1; off < 32; off <<= 1) {
        int t0 = __shfl_up_sync(0xffffffffu, s0, off);
        int t1 = __shfl_up_sync(0xffffffffu, s1, off);
        if (lane >= off) { s0 += t0; s1 += t1; }
    }
    int total_low = __shfl_sync(0xffffffffu, s0, 31);
    int total     = total_low + __shfl_sync(0xffffffffu, s1, 31);
    if (lane == 0) cnt[u] = total;

    int* out = nbr + (size_t)u * NBMAX;
    int o = s0 - c0;
    unsigned bits = w0;
    while (bits) {
        int b = __ffs(bits) - 1;
        bits &= bits - 1;
        out[o++] = lane * 32 + b;
    }
    o = total_low + s1 - c1;
    bits = w1;
    while (bits) {
        int b = __ffs(bits) - 1;
        bits &= bits - 1;
        out[o++] = (lane + 32) * 32 + b;
    }
}

// DEG=0: Rnew[u] = I_u | OR_{v in nbr(u)} Rold[v].  DEG=1: fused deg output.
template <int DEG>
__global__ void k_reach_iter(const int* __restrict__ nbr, const int* __restrict__ cnt,
                             const unsigned* __restrict__ Rold, unsigned* __restrict__ Rnew,
                             float* __restrict__ d) {
    __shared__ int sred[64];
    int u = blockIdx.x;
    int w = threadIdx.x;
    int n = __ldg(&cnt[u]);
    const int* list = nbr + (size_t)u * NBMAX;
    unsigned acc = ((u >> 5) == w) ? (1u << (u & 31)) : 0u;
    int j = 0;
    for (; j + 8 <= n; j += 8) {
        int v0 = __ldg(list + j + 0), v1 = __ldg(list + j + 1);
        int v2 = __ldg(list + j + 2), v3 = __ldg(list + j + 3);
        int v4 = __ldg(list + j + 4), v5 = __ldg(list + j + 5);
        int v6 = __ldg(list + j + 6), v7 = __ldg(list + j + 7);
        unsigned r0 = Rold[v0 * WORDS + w];
        unsigned r1 = Rold[v1 * WORDS + w];
        unsigned r2 = Rold[v2 * WORDS + w];
        unsigned r3 = Rold[v3 * WORDS + w];
        unsigned r4 = Rold[v4 * WORDS + w];
        unsigned r5 = Rold[v5 * WORDS + w];
        unsigned r6 = Rold[v6 * WORDS + w];
        unsigned r7 = Rold[v7 * WORDS + w];
        acc |= ((r0 | r1) | (r2 | r3)) | ((r4 | r5) | (r6 | r7));
    }
    for (; j + 4 <= n; j += 4) {
        int v0 = __ldg(list + j + 0), v1 = __ldg(list + j + 1);
        int v2 = __ldg(list + j + 2), v3 = __ldg(list + j + 3);
        acc |= (Rold[v0 * WORDS + w] | Rold[v1 * WORDS + w])
             | (Rold[v2 * WORDS + w] | Rold[v3 * WORDS + w]);
    }
    for (; j < n; ++j) acc |= Rold[__ldg(list + j) * WORDS + w];
    if (DEG == 0) {
        Rnew[u * WORDS + w] = acc;
    } else {
        sred[w] = __popc(acc);
        __syncthreads();
        if (w < 32) {
            int v = sred[w] + sred[w + 32];
            #pragma unroll
            for (int off = 16; off > 0; off >>= 1)
                v += __shfl_down_sync(0xffffffffu, v, off);
            if (w == 0) d[u] = (v > 0) ? rsqrtf((float)v) : 0.0f;
        }
    }
}

// ---- SpMM large C, fp16 gather (layer 2).  MODE 0: fp16 iterate out.
//      MODE 1: final fused epilogue, fp32 out = relu(w0*d*(u+wk*acc)+bias). ----
template <int MODE>
__global__ __launch_bounds__(256)
void k_spmm_h(const int* __restrict__ nbr, const int* __restrict__ cnt,
              const __half* __restrict__ vin, const float* __restrict__ uvec,
              __half* __restrict__ vout16, float* __restrict__ vout32,
              const float* __restrict__ wvec, int widx, int C,
              const float* __restrict__ dvec, const float* __restrict__ bias) {
    int u = blockIdx.x;
    int t = threadIdx.x;
    const int L = C >> 3;
    if (t >= L) return;
    int n = __ldg(&cnt[u]);
    const int* list = nbr + (size_t)u * NBMAX;
    float wk = __ldg(&wvec[widx]);

    float acc[8];
    #pragma unroll
    for (int q = 0; q < 8; ++q) acc[q] = 0.f;

    int j = 0;
    for (; j + 4 <= n; j += 4) {
        int v0 = __ldg(list + j + 0), v1 = __ldg(list + j + 1);
        int v2 = __ldg(list + j + 2), v3 = __ldg(list + j + 3);
        uint4 x0 = __ldg(reinterpret_cast<const uint4*>(vin + (size_t)v0 * C) + t);
        uint4 x1 = __ldg(reinterpret_cast<const uint4*>(vin + (size_t)v1 * C) + t);
        uint4 x2 = __ldg(reinterpret_cast<const uint4*>(vin + (size_t)v2 * C) + t);
        uint4 x3 = __ldg(reinterpret_cast<const uint4*>(vin + (size_t)v3 * C) + t);
        const __half2* h0 = reinterpret_cast<const __half2*>(&x0);
        const __half2* h1 = reinterpret_cast<const __half2*>(&x1);
        const __half2* h2 = reinterpret_cast<const __half2*>(&x2);
        const __half2* h3 = reinterpret_cast<const __half2*>(&x3);
        #pragma unroll
        for (int q = 0; q < 4; ++q) {
            float2 f0 = __half22float2(h0[q]);
            float2 f1 = __half22float2(h1[q]);
            float2 f2 = __half22float2(h2[q]);
            float2 f3 = __half22float2(h3[q]);
            acc[2 * q + 0] += (f0.x + f1.x) + (f2.x + f3.x);
            acc[2 * q + 1] += (f0.y + f1.y) + (f2.y + f3.y);
        }
    }
    for (; j < n; ++j) {
        int v = __ldg(list + j);
        uint4 x = __ldg(reinterpret_cast<const uint4*>(vin + (size_t)v * C) + t);
        const __half2* h = reinterpret_cast<const __half2*>(&x);
        #pragma unroll
        for (int q = 0; q < 4; ++q) {
            float2 f = __half22float2(h[q]);
            acc[2 * q + 0] += f.x;
            acc[2 * q + 1] += f.y;
        }
    }

    size_t base = (size_t)u * C + t * 8;
    float4 u0 = *reinterpret_cast<const float4*>(uvec + base);
    float4 u1 = *reinterpret_cast<const float4*>(uvec + base + 4);
    float o[8];
    o[0] = u0.x + wk * acc[0]; o[1] = u0.y + wk * acc[1];
    o[2] = u0.z + wk * acc[2]; o[3] = u0.w + wk * acc[3];
    o[4] = u1.x + wk * acc[4]; o[5] = u1.y + wk * acc[5];
    o[6] = u1.z + wk * acc[6]; o[7] = u1.w + wk * acc[7];
    if (MODE == 0) {
        __half2 hp[4];
        #pragma unroll
        for (int q = 0; q < 4; ++q)
            hp[q] = __floats2half2_rn(o[2 * q], o[2 * q + 1]);
        *(reinterpret_cast<uint4*>(vout16 + base)) = *reinterpret_cast<uint4*>(hp);
    } else {
        float w0d = __ldg(&wvec[0]) * __ldg(&dvec[u]);
        int cb = t * 8;
        float4 b0 = *reinterpret_cast<const float4*>(bias + cb);
        float4 b1 = *reinterpret_cast<const float4*>(bias + cb + 4);
        float r[8];
        r[0] = fmaxf(w0d * o[0] + b0.x, 0.f); r[1] = fmaxf(w0d * o[1] + b0.y, 0.f);
        r[2] = fmaxf(w0d * o[2] + b0.z, 0.f); r[3] = fmaxf(w0d * o[3] + b0.w, 0.f);
        r[4] = fmaxf(w0d * o[4] + b1.x, 0.f); r[5] = fmaxf(w0d * o[5] + b1.y, 0.f);
        r[6] = fmaxf(w0d * o[6] + b1.z, 0.f); r[7] = fmaxf(w0d * o[7] + b1.w, 0.f);
        *reinterpret_cast<float4*>(vout32 + base) = make_float4(r[0], r[1], r[2], r[3]);
        *reinterpret_cast<float4*>(vout32 + base + 4) = make_float4(r[4], r[5], r[6], r[7]);
    }
}

// ---- SpMM small C (layers 1/3), fp32 gathers (R12-proven), fused epilogues ----
// MODE 0: seed. vin = raw fp32 feat; u = d.*feat materialized; fp32 iterate out.
// MODE 1: mid hop, fp32 in/out.
// MODE 2: final layer-1: z = w0*d*(u+wk*acc); write split fp16 zhi/zlo.
// MODE 3: final layer-3: write fp32 relu(w0*d*(u+wk*acc)+bias).
template <int LPR, int MODE>
__global__ __launch_bounds__(256)
void k_spmm_s(const int* __restrict__ nbr, const int* __restrict__ cnt,
              const float* __restrict__ vin, float* __restrict__ uvec,
              float* __restrict__ vout,
              __half* __restrict__ zhi, __half* __restrict__ zlo,
              float* __restrict__ of,
              const float* __restrict__ wvec, int widx, int C,
              const float* __restrict__ dvec, const float* __restrict__ bias) {
    const int rpb = 256 / LPR;
    const int r = blockIdx.x * rpb + threadIdx.x / LPR;
    const int lane = threadIdx.x % LPR;
    int n = __ldg(&cnt[r]);
    const int* list = nbr + (size_t)r * NBMAX;
    float wk = __ldg(&wvec[widx]);

    float4 a0 = make_float4(0.f, 0.f, 0.f, 0.f);
    float4 a1 = make_float4(0.f, 0.f, 0.f, 0.f);
    float4 a2 = make_float4(0.f, 0.f, 0.f, 0.f);
    float4 a3 = make_float4(0.f, 0.f, 0.f, 0.f);

    int j = 0;
    for (; j + 4 <= n; j += 4) {
        int v0 = __ldg(list + j + 0), v1 = __ldg(list + j + 1);
        int v2 = __ldg(list + j + 2), v3 = __ldg(list + j + 3);
        float4 x0 = __ldg(reinterpret_cast<const float4*>(vin + (size_t)v0 * C) + lane);
        float4 x1 = __ldg(reinterpret_cast<const float4*>(vin + (size_t)v1 * C) + lane);
        float4 x2 = __ldg(reinterpret_cast<const float4*>(vin + (size_t)v2 * C) + lane);
        float4 x3 = __ldg(reinterpret_cast<const float4*>(vin + (size_t)v3 * C) + lane);
        if (MODE == 0) {
            float d0 = __ldg(&dvec[v0]), d1 = __ldg(&dvec[v1]);
            float d2 = __ldg(&dvec[v2]), d3 = __ldg(&dvec[v3]);
            x0.x *= d0; x0.y *= d0; x0.z *= d0; x0.w *= d0;
            x1.x *= d1; x1.y *= d1; x1.z *= d1; x1.w *= d1;
            x2.x *= d2; x2.y *= d2; x2.z *= d2; x2.w *= d2;
            x3.x *= d3; x3.y *= d3; x3.z *= d3; x3.w *= d3;
        }
        a0.x += x0.x; a0.y += x0.y; a0.z += x0.z; a0.w += x0.w;
        a1.x += x1.x; a1.y += x1.y; a1.z += x1.z; a1.w += x1.w;
        a2.x += x2.x; a2.y += x2.y; a2.z += x2.z; a2.w += x2.w;
        a3.x += x3.x; a3.y += x3.y; a3.z += x3.z; a3.w += x3.w;
    }
    for (; j < n; ++j) {
        int v = __ldg(list + j);
        float4 x = __ldg(reinterpret_cast<const float4*>(vin + (size_t)v * C) + lane);
        if (MODE == 0) {
            float dd = __ldg(&dvec[v]);
            x.x *= dd; x.y *= dd; x.z *= dd; x.w *= dd;
        }
        a0.x += x.x; a0.y += x.y; a0.z += x.z; a0.w += x.w;
    }
    float4 s;
    s.x = (a0.x + a1.x) + (a2.x + a3.x);
    s.y = (a0.y + a1.y) + (a2.y + a3.y);
    s.z = (a0.z + a1.z) + (a2.z + a3.z);
    s.w = (a0.w + a1.w) + (a2.w + a3.w);

    size_t base = (size_t)r * C + lane * 4;
    float4 uu;
    if (MODE == 0) {
        float dr = __ldg(&dvec[r]);
        uu = *(reinterpret_cast<const float4*>(vin + (size_t)r * C) + lane);
        uu.x *= dr; uu.y *= dr; uu.z *= dr; uu.w *= dr;
        *reinterpret_cast<float4*>(uvec + base) = uu;
    } else {
        uu = *reinterpret_cast<const float4*>(uvec + base);
    }
    float o0 = uu.x + wk * s.x;
    float o1 = uu.y + wk * s.y;
    float o2 = uu.z + wk * s.z;
    float o3 = uu.w + wk * s.w;

    if (MODE == 0 || MODE == 1) {
        *reinterpret_cast<float4*>(vout + base) = make_float4(o0, o1, o2, o3);
    } else if (MODE == 2) {
        float w0d = __ldg(&wvec[0]) * __ldg(&dvec[r]);
        float z0 = w0d * o0, z1 = w0d * o1, z2 = w0d * o2, z3 = w0d * o3;
        __half h0 = __float2half_rn(z0), h1 = __float2half_rn(z1);
        __half h2 = __float2half_rn(z2), h3 = __float2half_rn(z3);
        uint2 hp, lp;
        *reinterpret_cast<__half2*>(&hp.x) = __halves2half2(h0, h1);
        *reinterpret_cast<__half2*>(&hp.y) = __halves2half2(h2, h3);
        *reinterpret_cast<__half2*>(&lp.x) = __floats2half2_rn(z0 - __half2float(h0), z1 - __half2float(h1));
        *reinterpret_cast<__half2*>(&lp.y) = __floats2half2_rn(z2 - __half2float(h2), z3 - __half2float(h3));
        *(reinterpret_cast<uint2*>(zhi + base)) = hp;
        *(reinterpret_cast<uint2*>(zlo + base)) = lp;
    } else {
        float w0d = __ldg(&wvec[0]) * __ldg(&dvec[r]);
        float4 bb = *reinterpret_cast<const float4*>(bias + lane * 4);
        float4 ov;
        ov.x = fmaxf(w0d * o0 + bb.x, 0.f);
        ov.y = fmaxf(w0d * o1 + bb.y, 0.f);
        ov.z = fmaxf(w0d * o2 + bb.z, 0.f);
        ov.w = fmaxf(w0d * o3 + bb.w, 0.f);
        *reinterpret_cast<float4*>(of + base) = ov;
    }
}

__global__ void k_reduce_sk(const float* __restrict__ p, float* __restrict__ out, int n) {
    int i = blockIdx.x * blockDim.x + threadIdx.x;
    if (i < n) {
        float s = 0.f;
        #pragma unroll
        for (int k = 0; k < SK3; ++k) s += p[(size_t)k * n + i];
        out[i] = s;
    }
}

__global__ void k_tohalf2(const float* __restrict__ s1, __half* __restrict__ d1, int n1,
                          const float* __restrict__ s2, __half* __restrict__ d2, int n2) {
    int i = blockIdx.x * blockDim.x + threadIdx.x;
    if (i < n1) d1[i] = __float2half_rn(s1[i]);
    else {
        int j = i - n1;
        if (j < n2) d2[j] = __float2half_rn(s2[j]);
    }
}

// ---------------- cp.async helpers ----------------
__device__ __forceinline__ void cpasync16(void* s, const void* g, bool p) {
    unsigned sa = (unsigned)__cvta_generic_to_shared(s);
    asm volatile("cp.async.cg.shared.global [%0], [%1], 16, %2;"
                 :: "r"(sa), "l"(g), "r"(p ? 16 : 0));
}
__device__ __forceinline__ void cp_commit() { asm volatile("cp.async.commit_group;" ::: "memory"); }
__device__ __forceinline__ void cp_wait0()  { asm volatile("cp.async.wait_group 0;" ::: "memory"); }
__device__ __forceinline__ void cp_wait1()  { asm volatile("cp.async.wait_group 1;" ::: "memory"); }

// ---------------- fp16 tensor-core GEMM ----------------
#define TBM 128
#define TBN 128
#define TBK 32
#define ASTR 40
#define BSTR 136
#define ABUF (TBM * ASTR)
#define BBUF (TBK * BSTR)
#define SMEM_BYTES_2A ((4 * ABUF + 2 * BBUF) * 2)
#define SMEM_BYTES_1A ((2 * ABUF + 2 * BBUF) * 2)

__device__ __forceinline__ unsigned sptr(const void* p) {
    return (unsigned)__cvta_generic_to_shared(p);
}
__device__ __forceinline__ void ldsm4(unsigned& r0, unsigned& r1, unsigned& r2, unsigned& r3, unsigned a) {
    asm volatile("ldmatrix.sync.aligned.m8n8.x4.shared.b16 {%0,%1,%2,%3}, [%4];"
                 : "=r"(r0), "=r"(r1), "=r"(r2), "=r"(r3) : "r"(a));
}
__device__ __forceinline__ void ldsm4t(unsigned& r0, unsigned& r1, unsigned& r2, unsigned& r3, unsigned a) {
    asm volatile("ldmatrix.sync.aligned.m8n8.x4.trans.shared.b16 {%0,%1,%2,%3}, [%4];"
                 : "=r"(r0), "=r"(r1), "=r"(r2), "=r"(r3) : "r"(a));
}
__device__ __forceinline__ void mma16816h(float* c, const unsigned* a, unsigned b0, unsigned b1) {
    asm volatile("mma.sync.aligned.m16n8k16.row.col.f32.f16.f16.f32 "
                 "{%0,%1,%2,%3},{%4,%5,%6,%7},{%8,%9},{%0,%1,%2,%3};"
                 : "+f"(c[0]), "+f"(c[1]), "+f"(c[2]), "+f"(c[3])
                 : "r"(a[0]), "r"(a[1]), "r"(a[2]), "r"(a[3]), "r"(b0), "r"(b1));
}

// TWOA=1: D = (Ahi + Alo) * B.  TWOA=0: D = Ahi * B.
// EPI=1: +bias, relu, write single fp16 Chi.
// EPI=2: val = dv[row]*acc; write Cf (fp32 u) AND Chi (fp16 seed); col<Nd guard.  aux = dvec.
template<int EPI, int TWOA>
__global__ __launch_bounds__(256, 2)
void k_gemm_h(const __half* __restrict__ Ahi, const __half* __restrict__ Alo, int lda,
              const __half* __restrict__ Bh, int ldb,
              const float* __restrict__ aux,
              float* __restrict__ Cf, __half* __restrict__ Chi,
              int ldc, int Nd, int K) {
    extern __shared__ __half smh[];
    __half* sAh = smh;
    __half* sAl = sAh + 2 * ABUF;
    __half* sBh = TWOA ? (sAl + 2 * ABUF) : (sAh + 2 * ABUF);

    const int tid = threadIdx.x;
    const int wid = tid >> 5, lane = tid & 31;
    const int wm = (wid & 1) * 64;
    const int wn = (wid >> 1) * 32;
    const int m0 = blockIdx.y * TBM, n0 = blockIdx.x * TBN;

    const int a_r = tid >> 2;
    const int a_c = (tid & 3) << 3;
    const int b_r = tid >> 4;
    const int b_c = (tid & 15) << 3;
    const bool pb = (n0 + b_c) < Nd;

    const __half* gAh0 = Ahi + (size_t)(m0 + a_r) * lda + a_c;
    const __half* gAh1 = Ahi + (size_t)(m0 + a_r + 64) * lda + a_c;
    const __half* gAl0 = TWOA ? (Alo + (size_t)(m0 + a_r) * lda + a_c) : (const __half*)0;
    const __half* gAl1 = TWOA ? (Alo + (size_t)(m0 + a_r + 64) * lda + a_c) : (const __half*)0;
    const __half* gB0  = Bh + (size_t)b_r * ldb + n0 + b_c;
    const __half* gB1  = Bh + (size_t)(b_r + 16) * ldb + n0 + b_c;

    float acc[4][4][4];
    #pragma unroll
    for (int i = 0; i < 4; ++i)
        #pragma unroll
        for (int j = 0; j < 4; ++j)
            #pragma unroll
            for (int q = 0; q < 4; ++q) acc[i][j][q] = 0.f;

    const int KT = K / TBK;

    cpasync16(sAh + a_r * ASTR + a_c, gAh0, true);
    cpasync16(sAh + (a_r + 64) * ASTR + a_c, gAh1, true);
    if (TWOA) {
        cpasync16(sAl + a_r * ASTR + a_c, gAl0, true);
        cpasync16(sAl + (a_r + 64) * ASTR + a_c, gAl1, true);
    }
    cpasync16(sBh + b_r * BSTR + b_c, gB0, pb);
    cpasync16(sBh + (b_r + 16) * BSTR + b_c, gB1, pb);
    cp_commit();

    const int l16 = lane & 15;
    const int hsel = (lane >> 4) << 3;
    const int bg = lane >> 3, bl8 = lane & 7;
    const int bkoff = ((bg & 1) << 3) + bl8;
    const int bnoff = wn + ((bg >> 1) << 3);

    int buf = 0;
    for (int kt = 0; kt < KT; ++kt) {
        if (kt + 1 < KT) {
            int ko = (kt + 1) * TBK;
            int ob = (buf ^ 1);
            cpasync16(sAh + ob * ABUF + a_r * ASTR + a_c, gAh0 + ko, true);
            cpasync16(sAh + ob * ABUF + (a_r + 64) * ASTR + a_c, gAh1 + ko, true);
            if (TWOA) {
                cpasync16(sAl + ob * ABUF + a_r * ASTR + a_c, gAl0 + ko, true);
                cpasync16(sAl + ob * ABUF + (a_r + 64) * ASTR + a_c, gAl1 + ko, true);
            }
            cpasync16(sBh + ob * BBUF + b_r * BSTR + b_c, gB0 + (size_t)ko * ldb, pb);
            cpasync16(sBh + ob * BBUF + (b_r + 16) * BSTR + b_c, gB1 + (size_t)ko * ldb, pb);
            cp_commit();
            cp_wait1();
        } else {
            cp_wait0();
        }
        __syncthreads();

        #pragma unroll
        for (int ks = 0; ks < 2; ++ks) {
            const int ko = ks * 16;
            unsigned bh[8];
            {
                unsigned ab = sptr(sBh + buf * BBUF + (ko + bkoff) * BSTR + bnoff);
                ldsm4t(bh[0], bh[1], bh[2], bh[3], ab);
                ldsm4t(bh[4], bh[5], bh[6], bh[7], ab + 32);
            }
            #pragma unroll
            for (int mi = 0; mi < 4; ++mi) {
                unsigned ah[4];
                unsigned aa = sptr(sAh + buf * ABUF + (wm + mi * 16 + l16) * ASTR + ko + hsel);
                ldsm4(ah[0], ah[1], ah[2], ah[3], aa);
                unsigned alr[4];
                if (TWOA) {
                    unsigned aal = sptr(sAl + buf * ABUF + (wm + mi * 16 + l16) * ASTR + ko + hsel);
                    ldsm4(alr[0], alr[1], alr[2], alr[3], aal);
                }
                #pragma unroll
                for (int nj = 0; nj < 4; ++nj) {
                    int bi = (nj >> 1) * 4 + (nj & 1) * 2;
                    mma16816h(acc[mi][nj], ah, bh[bi], bh[bi + 1]);
                    if (TWOA) mma16816h(acc[mi][nj], alr, bh[bi], bh[bi + 1]);
                }
            }
        }
        __syncthreads();
        buf ^= 1;
    }

    const int er = lane >> 2;
    const int ec = (lane & 3) << 1;
    #pragma unroll
    for (int mi = 0; mi < 4; ++mi) {
        #pragma unroll
        for (int nj = 0; nj < 4; ++nj) {
            int row = m0 + wm + mi * 16 + er;
            int col = n0 + wn + nj * 8 + ec;
            float* a = acc[mi][nj];
            if (EPI == 1) {
                float bv0 = aux[col], bv1 = aux[col + 1];
                #pragma unroll
                for (int h = 0; h < 2; ++h) {
                    int r = row + h * 8;
                    float v0 = fmaxf(a[h * 2 + 0] + bv0, 0.f);
                    float v1 = fmaxf(a[h * 2 + 1] + bv1, 0.f);
                    *reinterpret_cast<__half2*>(&Chi[(size_t)r * Nd + col]) = __floats2half2_rn(v0, v1);
                }
            } else if (EPI == 2) {
                if (col < Nd) {
                    #pragma unroll
                    for (int h = 0; h < 2; ++h) {
                        int r = row + h * 8;
                        float dv = __ldg(&aux[r]);
                        float v0 = dv * a[h * 2 + 0];
                        float v1 = dv * a[h * 2 + 1];
                        *reinterpret_cast<float2*>(&Cf[(size_t)r * ldc + col]) = make_float2(v0, v1);
                        *reinterpret_cast<__half2*>(&Chi[(size_t)r * Nd + col]) = __floats2half2_rn(v0, v1);
                    }
                }
            }
        }
    }
}

// ---------------- fp32 GEMM (tiny GEMM3, split-K) ----------------
#define BM 128
#define BK 16

template<int BN_, int TN_>
__global__ __launch_bounds__(256)
void k_gemm(const float* __restrict__ A, int lda,
            const float* __restrict__ B, int ldb,
            float* __restrict__ Cout, int ldc,
            int Nd, int Kloop, int partStride) {
    __shared__ float As[2][BM][BK];
    __shared__ float Bs[2][BK][BN_];

    const int tid = threadIdx.x;
    const int tx = tid & 15;
    const int ty = tid >> 4;
    const int m0 = blockIdx.y * BM;
    const int n0 = blockIdx.x * BN_;

    A += (size_t)blockIdx.z * Kloop;
    B += (size_t)blockIdx.z * Kloop * ldb;
    Cout += (size_t)blockIdx.z * partStride;

    const int arow0 = tid >> 2;
    const int arow1 = arow0 + 64;
    const int ac4 = (tid & 3) * 4;
    const float* gA0 = A + (size_t)(m0 + arow0) * lda + ac4;
    const float* gA1 = A + (size_t)(m0 + arow1) * lda + ac4;

    const int BQ = BN_ / 4;
    const int bkr0 = tid / BQ;
    const int bc0 = (tid % BQ) * 4;
    const float* gB0 = B + (size_t)bkr0 * ldb + n0 + bc0;
    const bool bp0 = (n0 + bc0) < Nd;

    float acc[8][TN_];
    #pragma unroll
    for (int i = 0; i < 8; ++i)
        #pragma unroll
        for (int j = 0; j < TN_; ++j) acc[i][j] = 0.f;

    const int KT = Kloop / BK;

    cpasync16(&As[0][arow0][ac4], gA0, true);
    cpasync16(&As[0][arow1][ac4], gA1, true);
    cpasync16(&Bs[0][bkr0][bc0], gB0, bp0);
    cp_commit();

    int buf = 0;
    for (int kt = 0; kt < KT; ++kt) {
        if (kt + 1 < KT) {
            int ko = (kt + 1) * BK;
            cpasync16(&As[buf ^ 1][arow0][ac4], gA0 + ko, true);
            cpasync16(&As[buf ^ 1][arow1][ac4], gA1 + ko, true);
            cpasync16(&Bs[buf ^ 1][bkr0][bc0], gB0 + (size_t)ko * ldb, bp0);
            cp_commit();
            cp_wait1();
        } else {
            cp_wait0();
        }
        __syncthreads();

        #pragma unroll
        for (int k = 0; k < BK; ++k) {
            float a[8];
            #pragma unroll
            for (int i = 0; i < 8; ++i) a[i] = As[buf][ty * 8 + i][k];
            float b[TN_];
            #pragma unroll
            for (int j = 0; j < TN_; j += 4) {
                float4 v = *reinterpret_cast<const float4*>(&Bs[buf][k][tx * TN_ + j]);
                b[j] = v.x; b[j + 1] = v.y; b[j + 2] = v.z; b[j + 3] = v.w;
            }
            #pragma unroll
            for (int i = 0; i < 8; ++i)
                #pragma unroll
                for (int j = 0; j < TN_; ++j)
                    acc[i][j] += a[i] * b[j];
        }
        __syncthreads();
        buf ^= 1;
    }

    #pragma unroll
    for (int i = 0; i < 8; ++i) {
        int m = m0 + ty * 8 + i;
        #pragma unroll
        for (int j = 0; j < TN_; j += 4) {
            int n = n0 + tx * TN_ + j;
            if (n < Nd) {
                float4 v = make_float4(acc[i][j], acc[i][j + 1], acc[i][j + 2], acc[i][j + 3]);
                *reinterpret_cast<float4*>(&Cout[(size_t)m * ldc + n]) = v;
            }
        }
    }
}

// ---------------- host orchestration ----------------
extern "C" void kernel_launch(void* const* d_in, const int* in_sizes, int n_in,
                              void* d_out, int out_size) {
    const float* x  = (const float*)d_in[0];
    const int*   ei = (const int*)  d_in[1];
    const float* w1 = (const float*)d_in[2];
    const float* w2 = (const float*)d_in[3];
    const float* w3 = (const float*)d_in[4];
    const float* W1 = (const float*)d_in[5];
    const float* b1 = (const float*)d_in[6];
    const float* W2 = (const float*)d_in[7];
    const float* b2 = (const float*)d_in[8];
    const float* W3 = (const float*)d_in[9];
    const float* b3 = (const float*)d_in[10];
    float* out = (float*)d_out;

    unsigned *adj, *rA, *rB;
    int *nbr, *cnt;
    float *dvec, *u, *va, *vb, *h2, *g3, *g3p;
    __half *vha, *vhb, *zhi, *zlo, *w1h, *w2h, *h1h;
    cudaGetSymbolAddress((void**)&adj,  g_adj);
    cudaGetSymbolAddress((void**)&rA,   g_rA);
    cudaGetSymbolAddress((void**)&rB,   g_rB);
    cudaGetSymbolAddress((void**)&nbr,  g_nbr);
    cudaGetSymbolAddress((void**)&cnt,  g_cnt);
    cudaGetSymbolAddress((void**)&dvec, g_dvec);
    cudaGetSymbolAddress((void**)&u,    g_u);
    cudaGetSymbolAddress((void**)&va,   g_va);
    cudaGetSymbolAddress((void**)&vb,   g_vb);
    cudaGetSymbolAddress((void**)&h2,   g_h2);
    cudaGetSymbolAddress((void**)&g3,   g_g3);
    cudaGetSymbolAddress((void**)&g3p,  g_g3p);
    cudaGetSymbolAddress((void**)&vha,  g_vha);
    cudaGetSymbolAddress((void**)&vhb,  g_vhb);
    cudaGetSymbolAddress((void**)&zhi,  g_zhi);
    cudaGetSymbolAddress((void**)&zlo,  g_zlo);
    cudaGetSymbolAddress((void**)&w1h,  g_w1h);
    cudaGetSymbolAddress((void**)&w2h,  g_w2h);
    cudaGetSymbolAddress((void**)&h1h,  g_h1h);

    cudaFuncSetAttribute((const void*)k_gemm_h<1, 1>, cudaFuncAttributeMaxDynamicSharedMemorySize, SMEM_BYTES_2A);
    cudaFuncSetAttribute((const void*)k_gemm_h<2, 0>, cudaFuncAttributeMaxDynamicSharedMemorySize, SMEM_BYTES_1A);

    // ---- adjacency + lists + reach + deg ----
    k_zero_u32<<<(NN * WORDS + 255) / 256, 256>>>(adj, NN * WORDS);
    k_build_adj<<<EE / 256, 256>>>(ei, adj);
    k_build_fused<<<NN / 8, 256>>>(adj, nbr, cnt, rA);
    k_reach_iter<0><<<NN, 64>>>(nbr, cnt, rA, rB, (float*)0);
    k_reach_iter<0><<<NN, 64>>>(nbr, cnt, rB, rA, (float*)0);
    k_reach_iter<0><<<NN, 64>>>(nbr, cnt, rA, rB, (float*)0);
    k_reach_iter<1><<<NN, 64>>>(nbr, cnt, rB, rA, dvec);

    // weight conversions, single launch
    k_tohalf2<<<(C_IN * H1D + H1D * H2D + 255) / 256, 256>>>(W1, w1h, C_IN * H1D,
                                                             W2, w2h, H1D * H2D);

    // ---- layer 1: fp32 hop chain (final hop writes split-fp16 z); then GEMM1 ----
    {
        k_spmm_s<32, 0><<<NN / 8, 256>>>(nbr, cnt, x, u, va, (__half*)0, (__half*)0,
                                         (float*)0, w1, 5, C_IN, dvec, (const float*)0);
        k_spmm_s<32, 1><<<NN / 8, 256>>>(nbr, cnt, va, u, vb, (__half*)0, (__half*)0,
                                         (float*)0, w1, 4, C_IN, dvec, (const float*)0);
        k_spmm_s<32, 1><<<NN / 8, 256>>>(nbr, cnt, vb, u, va, (__half*)0, (__half*)0,
                                         (float*)0, w1, 3, C_IN, dvec, (const float*)0);
        k_spmm_s<32, 1><<<NN / 8, 256>>>(nbr, cnt, va, u, vb, (__half*)0, (__half*)0,
                                         (float*)0, w1, 2, C_IN, dvec, (const float*)0);
        k_spmm_s<32, 2><<<NN / 8, 256>>>(nbr, cnt, vb, u, (float*)0, zhi, zlo,
                                         (float*)0, w1, 1, C_IN, dvec, (const float*)0);
        dim3 grid(H1D / TBN, NN / TBM, 1);
        k_gemm_h<1, 1><<<grid, 256, SMEM_BYTES_2A>>>(zhi, zlo, C_IN, w1h, H1D,
                                                     b1, (float*)0, h1h, H1D, H1D, C_IN);
    }

    // ---- layer 2: GEMM2 (EPI=2 writes u + fp16 seed), 5 fp16 hops, fused final ----
    {
        dim3 grid((H2D + TBN - 1) / TBN, NN / TBM, 1);
        k_gemm_h<2, 0><<<grid, 256, SMEM_BYTES_1A>>>(h1h, (const __half*)0, H1D, w2h, H2D,
                                                     dvec, u, vha, H2D, H2D, H1D);
        k_spmm_h<0><<<NN, 256>>>(nbr, cnt, vha, u, vhb, (float*)0, w2, 5, H2D, (float*)0, (float*)0);
        k_spmm_h<0><<<NN, 256>>>(nbr, cnt, vhb, u, vha, (float*)0, w2, 4, H2D, (float*)0, (float*)0);
        k_spmm_h<0><<<NN, 256>>>(nbr, cnt, vha, u, vhb, (float*)0, w2, 3, H2D, (float*)0, (float*)0);
        k_spmm_h<0><<<NN, 256>>>(nbr, cnt, vhb, u, vha, (float*)0, w2, 2, H2D, (float*)0, (float*)0);
        k_spmm_h<1><<<NN, 256>>>(nbr, cnt, vha, u, (__half*)0, h2, w2, 1, H2D, dvec, b2);
    }

    // ---- layer 3: split-K GEMM, fp32 hop chain, fused bias+relu final ----
    {
        dim3 grid(1, NN / BM, SK3);
        k_gemm<64, 4><<<grid, 256>>>(h2, H2D, W3, ODIM, g3p, ODIM, ODIM, H2D / SK3, NN * ODIM);
        k_reduce_sk<<<(NN * ODIM + 255) / 256, 256>>>(g3p, g3, NN * ODIM);
        k_spmm_s<8, 0><<<NN / 32, 256>>>(nbr, cnt, g3, u, va, (__half*)0, (__half*)0,
                                         (float*)0, w3, 5, ODIM, dvec, (const float*)0);
        k_spmm_s<8, 1><<<NN / 32, 256>>>(nbr, cnt, va, u, vb, (__half*)0, (__half*)0,
                                         (float*)0, w3, 4, ODIM, dvec, (const float*)0);
        k_spmm_s<8, 1><<<NN / 32, 256>>>(nbr, cnt, vb, u, va, (__half*)0, (__half*)0,
                                         (float*)0, w3, 3, ODIM, dvec, (const float*)0);
        k_spmm_s<8, 1><<<NN / 32, 256>>>(nbr, cnt, va, u, vb, (__half*)0, (__half*)0,
                                         (float*)0, w3, 2, ODIM, dvec, (const float*)0);
        k_spmm_s<8, 3><<<NN / 32, 256>>>(nbr, cnt, vb, u, (float*)0, (__half*)0, (__half*)0,
                                         out, w3, 1, ODIM, dvec, b3);
    }
}

// round 15
// speedup vs baseline: 1.0378x; 1.0378x over previous
#include <cuda_runtime.h>
#include <cuda_fp16.h>

#define NN 2048
#define EE 65536
#define WORDS 64
#define NBMAX 2048
#define C_IN 128
#define H1D 3200
#define H2D 1600
#define ODIM 32
#define SK3 4

// ---------------- scratch (device globals) ----------------
__device__ unsigned g_adj[NN * WORDS];
__device__ unsigned g_rA [NN * WORDS];
__device__ unsigned g_rB [NN * WORDS];
__device__ int      g_nbr[(size_t)NN * NBMAX];
__device__ int      g_cnt[NN];
__device__ float    g_dvec[NN];
__device__ float    g_u  [NN * H2D];
__device__ float    g_va [NN * C_IN];
__device__ float    g_vb [NN * C_IN];
__device__ float    g_h2 [NN * H2D];
__device__ float    g_g3 [NN * ODIM];
__device__ float    g_g3p[SK3 * NN * ODIM];
// fp16 operands / iterates
__device__ __half g_vha[NN * H2D], g_vhb[NN * H2D];
__device__ __half g_zhi[NN * C_IN],  g_zlo[NN * C_IN];
__device__ __half g_w1h[C_IN * H1D];
__device__ __half g_w2h[H1D * H2D];
__device__ __half g_h1h[(size_t)NN * H1D];

// ---------------- utility kernels ----------------
__global__ void k_zero_u32(unsigned* p, int n) {
    int i = blockIdx.x * blockDim.x + threadIdx.x;
    if (i < n) p[i] = 0u;
}

__global__ void k_build_adj(const int* __restrict__ ei, unsigned* __restrict__ adj) {
    int e = blockIdx.x * blockDim.x + threadIdx.x;
    if (e < EE) {
        int src = ei[e];
        int dst = ei[EE + e];
        atomicOr(&adj[dst * WORDS + (src >> 5)], 1u << (src & 31));
    }
}

// Warp-per-row: build sorted neighbor list + write reach seed R = adj | diag.
__global__ __launch_bounds__(256)
void k_build_fused(const unsigned* __restrict__ adj,
                   int* __restrict__ nbr, int* __restrict__ cnt,
                   unsigned* __restrict__ R) {
    int warp = threadIdx.x >> 5;
    int lane = threadIdx.x & 31;
    int u = blockIdx.x * 8 + warp;
    const unsigned* row = adj + u * WORDS;
    unsigned w0 = row[lane];
    unsigned w1 = row[lane + 32];
    int dw = u >> 5;
    unsigned db = 1u << (u & 31);
    R[u * WORDS + lane]      = (dw == lane)      ? (w0 | db) : w0;
    R[u * WORDS + lane + 32] = (dw == lane + 32) ? (w1 | db) : w1;

    int c0 = __popc(w0), c1 = __popc(w1);
    int s0 = c0, s1 = c1;
    #pragma unroll
    for (int off = 1; off < 32; off <<= 1) {
        int t0 = __shfl_up_sync(0xffffffffu, s0, off);
        int t1 = __shfl_up_sync(0xffffffffu, s1, off);
        if (lane >= off) { s0 += t0; s1 += t1; }
    }
    int total_low = __shfl_sync(0xffffffffu, s0, 31);
    int total     = total_low + __shfl_sync(0xffffffffu, s1, 31);
    if (lane == 0) cnt[u] = total;

    int* out = nbr + (size_t)u * NBMAX;
    int o = s0 - c0;
    unsigned bits = w0;
    while (bits) {
        int b = __ffs(bits) - 1;
        bits &= bits - 1;
        out[o++] = lane * 32 + b;
    }
    o = total_low + s1 - c1;
    bits = w1;
    while (bits) {
        int b = __ffs(bits) - 1;
        bits &= bits - 1;
        out[o++] = (lane + 32) * 32 + b;
    }
}

// DEG=0: Rnew[u] = I_u | OR_{v in nbr(u)} Rold[v].  DEG=1: fused deg output.
template <int DEG>
__global__ void k_reach_iter(const int* __restrict__ nbr, const int* __restrict__ cnt,
                             const unsigned* __restrict__ Rold, unsigned* __restrict__ Rnew,
                             float* __restrict__ d) {
    __shared__ int sred[64];
    int u = blockIdx.x;
    int w = threadIdx.x;
    int n = __ldg(&cnt[u]);
    const int* list = nbr + (size_t)u * NBMAX;
    unsigned acc = ((u >> 5) == w) ? (1u << (u & 31)) : 0u;
    int j = 0;
    for (; j + 8 <= n; j += 8) {
        int v0 = __ldg(list + j + 0), v1 = __ldg(list + j + 1);
        int v2 = __ldg(list + j + 2), v3 = __ldg(list + j + 3);
        int v4 = __ldg(list + j + 4), v5 = __ldg(list + j + 5);
        int v6 = __ldg(list + j + 6), v7 = __ldg(list + j + 7);
        unsigned r0 = Rold[v0 * WORDS + w];
        unsigned r1 = Rold[v1 * WORDS + w];
        unsigned r2 = Rold[v2 * WORDS + w];
        unsigned r3 = Rold[v3 * WORDS + w];
        unsigned r4 = Rold[v4 * WORDS + w];
        unsigned r5 = Rold[v5 * WORDS + w];
        unsigned r6 = Rold[v6 * WORDS + w];
        unsigned r7 = Rold[v7 * WORDS + w];
        acc |= ((r0 | r1) | (r2 | r3)) | ((r4 | r5) | (r6 | r7));
    }
    for (; j + 4 <= n; j += 4) {
        int v0 = __ldg(list + j + 0), v1 = __ldg(list + j + 1);
        int v2 = __ldg(list + j + 2), v3 = __ldg(list + j + 3);
        acc |= (Rold[v0 * WORDS + w] | Rold[v1 * WORDS + w])
             | (Rold[v2 * WORDS + w] | Rold[v3 * WORDS + w]);
    }
    for (; j < n; ++j) acc |= Rold[__ldg(list + j) * WORDS + w];
    if (DEG == 0) {
        Rnew[u * WORDS + w] = acc;
    } else {
        sred[w] = __popc(acc);
        __syncthreads();
        if (w < 32) {
            int v = sred[w] + sred[w + 32];
            #pragma unroll
            for (int off = 16; off > 0; off >>= 1)
                v += __shfl_down_sync(0xffffffffu, v, off);
            if (w == 0) d[u] = (v > 0) ? rsqrtf((float)v) : 0.0f;
        }
    }
}

// ---- SpMM large C, fp16 gather (layer 2).  MODE 0: fp16 iterate out.
//      MODE 1: final fused epilogue, fp32 out = relu(w0*d*(u+wk*acc)+bias). ----
template <int MODE>
__global__ __launch_bounds__(256)
void k_spmm_h(const int* __restrict__ nbr, const int* __restrict__ cnt,
              const __half* __restrict__ vin, const float* __restrict__ uvec,
              __half* __restrict__ vout16, float* __restrict__ vout32,
              const float* __restrict__ wvec, int widx, int C,
              const float* __restrict__ dvec, const float* __restrict__ bias) {
    int u = blockIdx.x;
    int t = threadIdx.x;
    const int L = C >> 3;
    if (t >= L) return;
    int n = __ldg(&cnt[u]);
    const int* list = nbr + (size_t)u * NBMAX;
    float wk = __ldg(&wvec[widx]);

    float acc[8];
    #pragma unroll
    for (int q = 0; q < 8; ++q) acc[q] = 0.f;

    int j = 0;
    for (; j + 4 <= n; j += 4) {
        int v0 = __ldg(list + j + 0), v1 = __ldg(list + j + 1);
        int v2 = __ldg(list + j + 2), v3 = __ldg(list + j + 3);
        uint4 x0 = __ldg(reinterpret_cast<const uint4*>(vin + (size_t)v0 * C) + t);
        uint4 x1 = __ldg(reinterpret_cast<const uint4*>(vin + (size_t)v1 * C) + t);
        uint4 x2 = __ldg(reinterpret_cast<const uint4*>(vin + (size_t)v2 * C) + t);
        uint4 x3 = __ldg(reinterpret_cast<const uint4*>(vin + (size_t)v3 * C) + t);
        const __half2* h0 = reinterpret_cast<const __half2*>(&x0);
        const __half2* h1 = reinterpret_cast<const __half2*>(&x1);
        const __half2* h2 = reinterpret_cast<const __half2*>(&x2);
        const __half2* h3 = reinterpret_cast<const __half2*>(&x3);
        #pragma unroll
        for (int q = 0; q < 4; ++q) {
            float2 f0 = __half22float2(h0[q]);
            float2 f1 = __half22float2(h1[q]);
            float2 f2 = __half22float2(h2[q]);
            float2 f3 = __half22float2(h3[q]);
            acc[2 * q + 0] += (f0.x + f1.x) + (f2.x + f3.x);
            acc[2 * q + 1] += (f0.y + f1.y) + (f2.y + f3.y);
        }
    }
    for (; j < n; ++j) {
        int v = __ldg(list + j);
        uint4 x = __ldg(reinterpret_cast<const uint4*>(vin + (size_t)v * C) + t);
        const __half2* h = reinterpret_cast<const __half2*>(&x);
        #pragma unroll
        for (int q = 0; q < 4; ++q) {
            float2 f = __half22float2(h[q]);
            acc[2 * q + 0] += f.x;
            acc[2 * q + 1] += f.y;
        }
    }

    size_t base = (size_t)u * C + t * 8;
    float4 u0 = *reinterpret_cast<const float4*>(uvec + base);
    float4 u1 = *reinterpret_cast<const float4*>(uvec + base + 4);
    float o[8];
    o[0] = u0.x + wk * acc[0]; o[1] = u0.y + wk * acc[1];
    o[2] = u0.z + wk * acc[2]; o[3] = u0.w + wk * acc[3];
    o[4] = u1.x + wk * acc[4]; o[5] = u1.y + wk * acc[5];
    o[6] = u1.z + wk * acc[6]; o[7] = u1.w + wk * acc[7];
    if (MODE == 0) {
        __half2 hp[4];
        #pragma unroll
        for (int q = 0; q < 4; ++q)
            hp[q] = __floats2half2_rn(o[2 * q], o[2 * q + 1]);
        *(reinterpret_cast<uint4*>(vout16 + base)) = *reinterpret_cast<uint4*>(hp);
    } else {
        float w0d = __ldg(&wvec[0]) * __ldg(&dvec[u]);
        int cb = t * 8;
        float4 b0 = *reinterpret_cast<const float4*>(bias + cb);
        float4 b1 = *reinterpret_cast<const float4*>(bias + cb + 4);
        float r[8];
        r[0] = fmaxf(w0d * o[0] + b0.x, 0.f); r[1] = fmaxf(w0d * o[1] + b0.y, 0.f);
        r[2] = fmaxf(w0d * o[2] + b0.z, 0.f); r[3] = fmaxf(w0d * o[3] + b0.w, 0.f);
        r[4] = fmaxf(w0d * o[4] + b1.x, 0.f); r[5] = fmaxf(w0d * o[5] + b1.y, 0.f);
        r[6] = fmaxf(w0d * o[6] + b1.z, 0.f); r[7] = fmaxf(w0d * o[7] + b1.w, 0.f);
        *reinterpret_cast<float4*>(vout32 + base) = make_float4(r[0], r[1], r[2], r[3]);
        *reinterpret_cast<float4*>(vout32 + base + 4) = make_float4(r[4], r[5], r[6], r[7]);
    }
}

// ---- SpMM small C (layers 1/3), fp32 gathers, fused epilogues ----
template <int LPR, int MODE>
__global__ __launch_bounds__(256)
void k_spmm_s(const int* __restrict__ nbr, const int* __restrict__ cnt,
              const float* __restrict__ vin, float* __restrict__ uvec,
              float* __restrict__ vout,
              __half* __restrict__ zhi, __half* __restrict__ zlo,
              float* __restrict__ of,
              const float* __restrict__ wvec, int widx, int C,
              const float* __restrict__ dvec, const float* __restrict__ bias) {
    const int rpb = 256 / LPR;
    const int r = blockIdx.x * rpb + threadIdx.x / LPR;
    const int lane = threadIdx.x % LPR;
    int n = __ldg(&cnt[r]);
    const int* list = nbr + (size_t)r * NBMAX;
    float wk = __ldg(&wvec[widx]);

    float4 a0 = make_float4(0.f, 0.f, 0.f, 0.f);
    float4 a1 = make_float4(0.f, 0.f, 0.f, 0.f);
    float4 a2 = make_float4(0.f, 0.f, 0.f, 0.f);
    float4 a3 = make_float4(0.f, 0.f, 0.f, 0.f);

    int j = 0;
    for (; j + 4 <= n; j += 4) {
        int v0 = __ldg(list + j + 0), v1 = __ldg(list + j + 1);
        int v2 = __ldg(list + j + 2), v3 = __ldg(list + j + 3);
        float4 x0 = __ldg(reinterpret_cast<const float4*>(vin + (size_t)v0 * C) + lane);
        float4 x1 = __ldg(reinterpret_cast<const float4*>(vin + (size_t)v1 * C) + lane);
        float4 x2 = __ldg(reinterpret_cast<const float4*>(vin + (size_t)v2 * C) + lane);
        float4 x3 = __ldg(reinterpret_cast<const float4*>(vin + (size_t)v3 * C) + lane);
        if (MODE == 0) {
            float d0 = __ldg(&dvec[v0]), d1 = __ldg(&dvec[v1]);
            float d2 = __ldg(&dvec[v2]), d3 = __ldg(&dvec[v3]);
            x0.x *= d0; x0.y *= d0; x0.z *= d0; x0.w *= d0;
            x1.x *= d1; x1.y *= d1; x1.z *= d1; x1.w *= d1;
            x2.x *= d2; x2.y *= d2; x2.z *= d2; x2.w *= d2;
            x3.x *= d3; x3.y *= d3; x3.z *= d3; x3.w *= d3;
        }
        a0.x += x0.x; a0.y += x0.y; a0.z += x0.z; a0.w += x0.w;
        a1.x += x1.x; a1.y += x1.y; a1.z += x1.z; a1.w += x1.w;
        a2.x += x2.x; a2.y += x2.y; a2.z += x2.z; a2.w += x2.w;
        a3.x += x3.x; a3.y += x3.y; a3.z += x3.z; a3.w += x3.w;
    }
    for (; j < n; ++j) {
        int v = __ldg(list + j);
        float4 x = __ldg(reinterpret_cast<const float4*>(vin + (size_t)v * C) + lane);
        if (MODE == 0) {
            float dd = __ldg(&dvec[v]);
            x.x *= dd; x.y *= dd; x.z *= dd; x.w *= dd;
        }
        a0.x += x.x; a0.y += x.y; a0.z += x.z; a0.w += x.w;
    }
    float4 s;
    s.x = (a0.x + a1.x) + (a2.x + a3.x);
    s.y = (a0.y + a1.y) + (a2.y + a3.y);
    s.z = (a0.z + a1.z) + (a2.z + a3.z);
    s.w = (a0.w + a1.w) + (a2.w + a3.w);

    size_t base = (size_t)r * C + lane * 4;
    float4 uu;
    if (MODE == 0) {
        float dr = __ldg(&dvec[r]);
        uu = *(reinterpret_cast<const float4*>(vin + (size_t)r * C) + lane);
        uu.x *= dr; uu.y *= dr; uu.z *= dr; uu.w *= dr;
        *reinterpret_cast<float4*>(uvec + base) = uu;
    } else {
        uu = *reinterpret_cast<const float4*>(uvec + base);
    }
    float o0 = uu.x + wk * s.x;
    float o1 = uu.y + wk * s.y;
    float o2 = uu.z + wk * s.z;
    float o3 = uu.w + wk * s.w;

    if (MODE == 0 || MODE == 1) {
        *reinterpret_cast<float4*>(vout + base) = make_float4(o0, o1, o2, o3);
    } else if (MODE == 2) {
        float w0d = __ldg(&wvec[0]) * __ldg(&dvec[r]);
        float z0 = w0d * o0, z1 = w0d * o1, z2 = w0d * o2, z3 = w0d * o3;
        __half h0 = __float2half_rn(z0), h1 = __float2half_rn(z1);
        __half h2 = __float2half_rn(z2), h3 = __float2half_rn(z3);
        uint2 hp, lp;
        *reinterpret_cast<__half2*>(&hp.x) = __halves2half2(h0, h1);
        *reinterpret_cast<__half2*>(&hp.y) = __halves2half2(h2, h3);
        *reinterpret_cast<__half2*>(&lp.x) = __floats2half2_rn(z0 - __half2float(h0), z1 - __half2float(h1));
        *reinterpret_cast<__half2*>(&lp.y) = __floats2half2_rn(z2 - __half2float(h2), z3 - __half2float(h3));
        *(reinterpret_cast<uint2*>(zhi + base)) = hp;
        *(reinterpret_cast<uint2*>(zlo + base)) = lp;
    } else {
        float w0d = __ldg(&wvec[0]) * __ldg(&dvec[r]);
        float4 bb = *reinterpret_cast<const float4*>(bias + lane * 4);
        float4 ov;
        ov.x = fmaxf(w0d * o0 + bb.x, 0.f);
        ov.y = fmaxf(w0d * o1 + bb.y, 0.f);
        ov.z = fmaxf(w0d * o2 + bb.z, 0.f);
        ov.w = fmaxf(w0d * o3 + bb.w, 0.f);
        *reinterpret_cast<float4*>(of + base) = ov;
    }
}

__global__ void k_reduce_sk(const float* __restrict__ p, float* __restrict__ out, int n) {
    int i = blockIdx.x * blockDim.x + threadIdx.x;
    if (i < n) {
        float s = 0.f;
        #pragma unroll
        for (int k = 0; k < SK3; ++k) s += p[(size_t)k * n + i];
        out[i] = s;
    }
}

__global__ void k_tohalf2(const float* __restrict__ s1, __half* __restrict__ d1, int n1,
                          const float* __restrict__ s2, __half* __restrict__ d2, int n2) {
    int i = blockIdx.x * blockDim.x + threadIdx.x;
    if (i < n1) d1[i] = __float2half_rn(s1[i]);
    else {
        int j = i - n1;
        if (j < n2) d2[j] = __float2half_rn(s2[j]);
    }
}

// ---------------- cp.async helpers ----------------
__device__ __forceinline__ void cpasync16(void* s, const void* g, bool p) {
    unsigned sa = (unsigned)__cvta_generic_to_shared(s);
    asm volatile("cp.async.cg.shared.global [%0], [%1], 16, %2;"
                 :: "r"(sa), "l"(g), "r"(p ? 16 : 0));
}
__device__ __forceinline__ void cp_commit() { asm volatile("cp.async.commit_group;" ::: "memory"); }
__device__ __forceinline__ void cp_wait0()  { asm volatile("cp.async.wait_group 0;" ::: "memory"); }
__device__ __forceinline__ void cp_wait1()  { asm volatile("cp.async.wait_group 1;" ::: "memory"); }

// ---------------- fp16 tensor-core GEMM, STAGES-deep cp.async pipeline ----------------
#define TBM 128
#define TBN 128
#define TBK 32
#define ASTR 40
#define BSTR 136
#define ABUF (TBM * ASTR)
#define BBUF (TBK * BSTR)
// smem bytes: ((TWOA?2:1)*S*ABUF + S*BBUF) * 2
#define SMEM_G1 ((2 * 2 * ABUF + 2 * BBUF) * 2)   // GEMM1: TWOA=1, S=2
#define SMEM_G2 ((3 * ABUF + 3 * BBUF) * 2)       // GEMM2: TWOA=0, S=3

__device__ __forceinline__ unsigned sptr(const void* p) {
    return (unsigned)__cvta_generic_to_shared(p);
}
__device__ __forceinline__ void ldsm4(unsigned& r0, unsigned& r1, unsigned& r2, unsigned& r3, unsigned a) {
    asm volatile("ldmatrix.sync.aligned.m8n8.x4.shared.b16 {%0,%1,%2,%3}, [%4];"
                 : "=r"(r0), "=r"(r1), "=r"(r2), "=r"(r3) : "r"(a));
}
__device__ __forceinline__ void ldsm4t(unsigned& r0, unsigned& r1, unsigned& r2, unsigned& r3, unsigned a) {
    asm volatile("ldmatrix.sync.aligned.m8n8.x4.trans.shared.b16 {%0,%1,%2,%3}, [%4];"
                 : "=r"(r0), "=r"(r1), "=r"(r2), "=r"(r3) : "r"(a));
}
__device__ __forceinline__ void mma16816h(float* c, const unsigned* a, unsigned b0, unsigned b1) {
    asm volatile("mma.sync.aligned.m16n8k16.row.col.f32.f16.f16.f32 "
                 "{%0,%1,%2,%3},{%4,%5,%6,%7},{%8,%9},{%0,%1,%2,%3};"
                 : "+f"(c[0]), "+f"(c[1]), "+f"(c[2]), "+f"(c[3])
                 : "r"(a[0]), "r"(a[1]), "r"(a[2]), "r"(a[3]), "r"(b0), "r"(b1));
}

// TWOA=1: D = (Ahi + Alo) * B.  TWOA=0: D = Ahi * B.
// EPI=1: +bias, relu, write single fp16 Chi.
// EPI=2: val = dv[row]*acc; write Cf (fp32 u) AND Chi (fp16 seed); col<Nd guard.  aux = dvec.
template<int EPI, int TWOA, int STAGES>
__global__ __launch_bounds__(256, 2)
void k_gemm_h(const __half* __restrict__ Ahi, const __half* __restrict__ Alo, int lda,
              const __half* __restrict__ Bh, int ldb,
              const float* __restrict__ aux,
              float* __restrict__ Cf, __half* __restrict__ Chi,
              int ldc, int Nd, int K) {
    extern __shared__ __half smh[];
    __half* sAh = smh;
    __half* sAl = sAh + STAGES * ABUF;                  // only used when TWOA
    __half* sBh = TWOA ? (sAl + STAGES * ABUF) : (sAh + STAGES * ABUF);

    const int tid = threadIdx.x;
    const int wid = tid >> 5, lane = tid & 31;
    const int wm = (wid & 1) * 64;
    const int wn = (wid >> 1) * 32;
    const int m0 = blockIdx.y * TBM, n0 = blockIdx.x * TBN;

    const int a_r = tid >> 2;
    const int a_c = (tid & 3) << 3;
    const int b_r = tid >> 4;
    const int b_c = (tid & 15) << 3;
    const bool pb = (n0 + b_c) < Nd;

    const __half* gAh0 = Ahi + (size_t)(m0 + a_r) * lda + a_c;
    const __half* gAh1 = Ahi + (size_t)(m0 + a_r + 64) * lda + a_c;
    const __half* gAl0 = TWOA ? (Alo + (size_t)(m0 + a_r) * lda + a_c) : (const __half*)0;
    const __half* gAl1 = TWOA ? (Alo + (size_t)(m0 + a_r + 64) * lda + a_c) : (const __half*)0;
    const __half* gB0  = Bh + (size_t)b_r * ldb + n0 + b_c;
    const __half* gB1  = Bh + (size_t)(b_r + 16) * ldb + n0 + b_c;

    auto issue_tile = [&](int sbuf, int ko) {
        cpasync16(sAh + sbuf * ABUF + a_r * ASTR + a_c, gAh0 + ko, true);
        cpasync16(sAh + sbuf * ABUF + (a_r + 64) * ASTR + a_c, gAh1 + ko, true);
        if (TWOA) {
            cpasync16(sAl + sbuf * ABUF + a_r * ASTR + a_c, gAl0 + ko, true);
            cpasync16(sAl + sbuf * ABUF + (a_r + 64) * ASTR + a_c, gAl1 + ko, true);
        }
        cpasync16(sBh + sbuf * BBUF + b_r * BSTR + b_c, gB0 + (size_t)ko * ldb, pb);
        cpasync16(sBh + sbuf * BBUF + (b_r + 16) * BSTR + b_c, gB1 + (size_t)ko * ldb, pb);
    };

    float acc[4][4][4];
    #pragma unroll
    for (int i = 0; i < 4; ++i)
        #pragma unroll
        for (int j = 0; j < 4; ++j)
            #pragma unroll
            for (int q = 0; q < 4; ++q) acc[i][j][q] = 0.f;

    const int KT = K / TBK;

    // prologue: issue tiles 0..STAGES-2, one commit group each
    #pragma unroll
    for (int s = 0; s < STAGES - 1; ++s) {
        if (s < KT) issue_tile(s, s * TBK);
        cp_commit();
    }

    const int l16 = lane & 15;
    const int hsel = (lane >> 4) << 3;
    const int bg = lane >> 3, bl8 = lane & 7;
    const int bkoff = ((bg & 1) << 3) + bl8;
    const int bnoff = wn + ((bg >> 1) << 3);

    for (int kt = 0; kt < KT; ++kt) {
        asm volatile("cp.async.wait_group %0;" :: "n"(STAGES - 2) : "memory");
        __syncthreads();
        // prefetch tile kt+STAGES-1 into the buffer freed by tile kt-1
        int pf = kt + STAGES - 1;
        if (pf < KT) issue_tile(pf % STAGES, pf * TBK);
        cp_commit();

        const int buf = kt % STAGES;
        #pragma unroll
        for (int ks = 0; ks < 2; ++ks) {
            const int ko = ks * 16;
            unsigned bh[8];
            {
                unsigned ab = sptr(sBh + buf * BBUF + (ko + bkoff) * BSTR + bnoff);
                ldsm4t(bh[0], bh[1], bh[2], bh[3], ab);
                ldsm4t(bh[4], bh[5], bh[6], bh[7], ab + 32);
            }
            #pragma unroll
            for (int mi = 0; mi < 4; ++mi) {
                unsigned ah[4];
                unsigned aa = sptr(sAh + buf * ABUF + (wm + mi * 16 + l16) * ASTR + ko + hsel);
                ldsm4(ah[0], ah[1], ah[2], ah[3], aa);
                unsigned alr[4];
                if (TWOA) {
                    unsigned aal = sptr(sAl + buf * ABUF + (wm + mi * 16 + l16) * ASTR + ko + hsel);
                    ldsm4(alr[0], alr[1], alr[2], alr[3], aal);
                }
                #pragma unroll
                for (int nj = 0; nj < 4; ++nj) {
                    int bi = (nj >> 1) * 4 + (nj & 1) * 2;
                    mma16816h(acc[mi][nj], ah, bh[bi], bh[bi + 1]);
                    if (TWOA) mma16816h(acc[mi][nj], alr, bh[bi], bh[bi + 1]);
                }
            }
        }
    }

    const int er = lane >> 2;
    const int ec = (lane & 3) << 1;
    #pragma unroll
    for (int mi = 0; mi < 4; ++mi) {
        #pragma unroll
        for (int nj = 0; nj < 4; ++nj) {
            int row = m0 + wm + mi * 16 + er;
            int col = n0 + wn + nj * 8 + ec;
            float* a = acc[mi][nj];
            if (EPI == 1) {
                float bv0 = aux[col], bv1 = aux[col + 1];
                #pragma unroll
                for (int h = 0; h < 2; ++h) {
                    int r = row + h * 8;
                    float v0 = fmaxf(a[h * 2 + 0] + bv0, 0.f);
                    float v1 = fmaxf(a[h * 2 + 1] + bv1, 0.f);
                    *reinterpret_cast<__half2*>(&Chi[(size_t)r * Nd + col]) = __floats2half2_rn(v0, v1);
                }
            } else if (EPI == 2) {
                if (col < Nd) {    // guard: grid.x overshoots Nd by one partial tile
                    #pragma unroll
                    for (int h = 0; h < 2; ++h) {
                        int r = row + h * 8;
                        float dv = __ldg(&aux[r]);
                        float v0 = dv * a[h * 2 + 0];
                        float v1 = dv * a[h * 2 + 1];
                        *reinterpret_cast<float2*>(&Cf[(size_t)r * ldc + col]) = make_float2(v0, v1);
                        *reinterpret_cast<__half2*>(&Chi[(size_t)r * Nd + col]) = __floats2half2_rn(v0, v1);
                    }
                }
            }
        }
    }
}

// ---------------- fp32 GEMM (tiny GEMM3, split-K) ----------------
#define BM 128
#define BK 16

template<int BN_, int TN_>
__global__ __launch_bounds__(256)
void k_gemm(const float* __restrict__ A, int lda,
            const float* __restrict__ B, int ldb,
            float* __restrict__ Cout, int ldc,
            int Nd, int Kloop, int partStride) {
    __shared__ float As[2][BM][BK];
    __shared__ float Bs[2][BK][BN_];

    const int tid = threadIdx.x;
    const int tx = tid & 15;
    const int ty = tid >> 4;
    const int m0 = blockIdx.y * BM;
    const int n0 = blockIdx.x * BN_;

    A += (size_t)blockIdx.z * Kloop;
    B += (size_t)blockIdx.z * Kloop * ldb;
    Cout += (size_t)blockIdx.z * partStride;

    const int arow0 = tid >> 2;
    const int arow1 = arow0 + 64;
    const int ac4 = (tid & 3) * 4;
    const float* gA0 = A + (size_t)(m0 + arow0) * lda + ac4;
    const float* gA1 = A + (size_t)(m0 + arow1) * lda + ac4;

    const int BQ = BN_ / 4;
    const int bkr0 = tid / BQ;
    const int bc0 = (tid % BQ) * 4;
    const float* gB0 = B + (size_t)bkr0 * ldb + n0 + bc0;
    const bool bp0 = (n0 + bc0) < Nd;

    float acc[8][TN_];
    #pragma unroll
    for (int i = 0; i < 8; ++i)
        #pragma unroll
        for (int j = 0; j < TN_; ++j) acc[i][j] = 0.f;

    const int KT = Kloop / BK;

    cpasync16(&As[0][arow0][ac4], gA0, true);
    cpasync16(&As[0][arow1][ac4], gA1, true);
    cpasync16(&Bs[0][bkr0][bc0], gB0, bp0);
    cp_commit();

    int buf = 0;
    for (int kt = 0; kt < KT; ++kt) {
        if (kt + 1 < KT) {
            int ko = (kt + 1) * BK;
            cpasync16(&As[buf ^ 1][arow0][ac4], gA0 + ko, true);
            cpasync16(&As[buf ^ 1][arow1][ac4], gA1 + ko, true);
            cpasync16(&Bs[buf ^ 1][bkr0][bc0], gB0 + (size_t)ko * ldb, bp0);
            cp_commit();
            cp_wait1();
        } else {
            cp_wait0();
        }
        __syncthreads();

        #pragma unroll
        for (int k = 0; k < BK; ++k) {
            float a[8];
            #pragma unroll
            for (int i = 0; i < 8; ++i) a[i] = As[buf][ty * 8 + i][k];
            float b[TN_];
            #pragma unroll
            for (int j = 0; j < TN_; j += 4) {
                float4 v = *reinterpret_cast<const float4*>(&Bs[buf][k][tx * TN_ + j]);
                b[j] = v.x; b[j + 1] = v.y; b[j + 2] = v.z; b[j + 3] = v.w;
            }
            #pragma unroll
            for (int i = 0; i < 8; ++i)
                #pragma unroll
                for (int j = 0; j < TN_; ++j)
                    acc[i][j] += a[i] * b[j];
        }
        __syncthreads();
        buf ^= 1;
    }

    #pragma unroll
    for (int i = 0; i < 8; ++i) {
        int m = m0 + ty * 8 + i;
        #pragma unroll
        for (int j = 0; j < TN_; j += 4) {
            int n = n0 + tx * TN_ + j;
            if (n < Nd) {
                float4 v = make_float4(acc[i][j], acc[i][j + 1], acc[i][j + 2], acc[i][j + 3]);
                *reinterpret_cast<float4*>(&Cout[(size_t)m * ldc + n]) = v;
            }
        }
    }
}

// ---------------- host orchestration ----------------
extern "C" void kernel_launch(void* const* d_in, const int* in_sizes, int n_in,
                              void* d_out, int out_size) {
    const float* x  = (const float*)d_in[0];
    const int*   ei = (const int*)  d_in[1];
    const float* w1 = (const float*)d_in[2];
    const float* w2 = (const float*)d_in[3];
    const float* w3 = (const float*)d_in[4];
    const float* W1 = (const float*)d_in[5];
    const float* b1 = (const float*)d_in[6];
    const float* W2 = (const float*)d_in[7];
    const float* b2 = (const float*)d_in[8];
    const float* W3 = (const float*)d_in[9];
    const float* b3 = (const float*)d_in[10];
    float* out = (float*)d_out;

    unsigned *adj, *rA, *rB;
    int *nbr, *cnt;
    float *dvec, *u, *va, *vb, *h2, *g3, *g3p;
    __half *vha, *vhb, *zhi, *zlo, *w1h, *w2h, *h1h;
    cudaGetSymbolAddress((void**)&adj,  g_adj);
    cudaGetSymbolAddress((void**)&rA,   g_rA);
    cudaGetSymbolAddress((void**)&rB,   g_rB);
    cudaGetSymbolAddress((void**)&nbr,  g_nbr);
    cudaGetSymbolAddress((void**)&cnt,  g_cnt);
    cudaGetSymbolAddress((void**)&dvec, g_dvec);
    cudaGetSymbolAddress((void**)&u,    g_u);
    cudaGetSymbolAddress((void**)&va,   g_va);
    cudaGetSymbolAddress((void**)&vb,   g_vb);
    cudaGetSymbolAddress((void**)&h2,   g_h2);
    cudaGetSymbolAddress((void**)&g3,   g_g3);
    cudaGetSymbolAddress((void**)&g3p,  g_g3p);
    cudaGetSymbolAddress((void**)&vha,  g_vha);
    cudaGetSymbolAddress((void**)&vhb,  g_vhb);
    cudaGetSymbolAddress((void**)&zhi,  g_zhi);
    cudaGetSymbolAddress((void**)&zlo,  g_zlo);
    cudaGetSymbolAddress((void**)&w1h,  g_w1h);
    cudaGetSymbolAddress((void**)&w2h,  g_w2h);
    cudaGetSymbolAddress((void**)&h1h,  g_h1h);

    cudaFuncSetAttribute((const void*)k_gemm_h<1, 1, 2>, cudaFuncAttributeMaxDynamicSharedMemorySize, SMEM_G1);
    cudaFuncSetAttribute((const void*)k_gemm_h<2, 0, 3>, cudaFuncAttributeMaxDynamicSharedMemorySize, SMEM_G2);

    // ---- adjacency + lists + reach + deg ----
    k_zero_u32<<<(NN * WORDS + 255) / 256, 256>>>(adj, NN * WORDS);
    k_build_adj<<<EE / 256, 256>>>(ei, adj);
    k_build_fused<<<NN / 8, 256>>>(adj, nbr, cnt, rA);
    k_reach_iter<0><<<NN, 64>>>(nbr, cnt, rA, rB, (float*)0);
    k_reach_iter<0><<<NN, 64>>>(nbr, cnt, rB, rA, (float*)0);
    k_reach_iter<0><<<NN, 64>>>(nbr, cnt, rA, rB, (float*)0);
    k_reach_iter<1><<<NN, 64>>>(nbr, cnt, rB, rA, dvec);

    // weight conversions, single launch
    k_tohalf2<<<(C_IN * H1D + H1D * H2D + 255) / 256, 256>>>(W1, w1h, C_IN * H1D,
                                                             W2, w2h, H1D * H2D);

    // ---- layer 1: fp32 hop chain (final hop writes split-fp16 z); then GEMM1 ----
    {
        k_spmm_s<32, 0><<<NN / 8, 256>>>(nbr, cnt, x, u, va, (__half*)0, (__half*)0,
                                         (float*)0, w1, 5, C_IN, dvec, (const float*)0);
        k_spmm_s<32, 1><<<NN / 8, 256>>>(nbr, cnt, va, u, vb, (__half*)0, (__half*)0,
                                         (float*)0, w1, 4, C_IN, dvec, (const float*)0);
        k_spmm_s<32, 1><<<NN / 8, 256>>>(nbr, cnt, vb, u, va, (__half*)0, (__half*)0,
                                         (float*)0, w1, 3, C_IN, dvec, (const float*)0);
        k_spmm_s<32, 1><<<NN / 8, 256>>>(nbr, cnt, va, u, vb, (__half*)0, (__half*)0,
                                         (float*)0, w1, 2, C_IN, dvec, (const float*)0);
        k_spmm_s<32, 2><<<NN / 8, 256>>>(nbr, cnt, vb, u, (float*)0, zhi, zlo,
                                         (float*)0, w1, 1, C_IN, dvec, (const float*)0);
        dim3 grid(H1D / TBN, NN / TBM, 1);
        k_gemm_h<1, 1, 2><<<grid, 256, SMEM_G1>>>(zhi, zlo, C_IN, w1h, H1D,
                                                  b1, (float*)0, h1h, H1D, H1D, C_IN);
    }

    // ---- layer 2: GEMM2 (3-stage pipeline; EPI=2 writes u + fp16 seed), 5 fp16 hops ----
    {
        dim3 grid((H2D + TBN - 1) / TBN, NN / TBM, 1);
        k_gemm_h<2, 0, 3><<<grid, 256, SMEM_G2>>>(h1h, (const __half*)0, H1D, w2h, H2D,
                                                  dvec, u, vha, H2D, H2D, H1D);
        k_spmm_h<0><<<NN, 256>>>(nbr, cnt, vha, u, vhb, (float*)0, w2, 5, H2D, (float*)0, (float*)0);
        k_spmm_h<0><<<NN, 256>>>(nbr, cnt, vhb, u, vha, (float*)0, w2, 4, H2D, (float*)0, (float*)0);
        k_spmm_h<0><<<NN, 256>>>(nbr, cnt, vha, u, vhb, (float*)0, w2, 3, H2D, (float*)0, (float*)0);
        k_spmm_h<0><<<NN, 256>>>(nbr, cnt, vhb, u, vha, (float*)0, w2, 2, H2D, (float*)0, (float*)0);
        k_spmm_h<1><<<NN, 256>>>(nbr, cnt, vha, u, (__half*)0, h2, w2, 1, H2D, dvec, b2);
    }

    // ---- layer 3: split-K GEMM, fp32 hop chain, fused bias+relu final ----
    {
        dim3 grid(1, NN / BM, SK3);
        k_gemm<64, 4><<<grid, 256>>>(h2, H2D, W3, ODIM, g3p, ODIM, ODIM, H2D / SK3, NN * ODIM);
        k_reduce_sk<<<(NN * ODIM + 255) / 256, 256>>>(g3p, g3, NN * ODIM);
        k_spmm_s<8, 0><<<NN / 32, 256>>>(nbr, cnt, g3, u, va, (__half*)0, (__half*)0,
                                         (float*)0, w3, 5, ODIM, dvec, (const float*)0);
        k_spmm_s<8, 1><<<NN / 32, 256>>>(nbr, cnt, va, u, vb, (__half*)0, (__half*)0,
                                         (float*)0, w3, 4, ODIM, dvec, (const float*)0);
        k_spmm_s<8, 1><<<NN / 32, 256>>>(nbr, cnt, vb, u, va, (__half*)0, (__half*)0,
                                         (float*)0, w3, 3, ODIM, dvec, (const float*)0);
        k_spmm_s<8, 1><<<NN / 32, 256>>>(nbr, cnt, va, u, vb, (__half*)0, (__half*)0,
                                         (float*)0, w3, 2, ODIM, dvec, (const float*)0);
        k_spmm_s<8, 3><<<NN / 32, 256>>>(nbr, cnt, vb, u, (float*)0, (__half*)0, (__half*)0,
                                         out, w3, 1, ODIM, dvec, b3);
    }
}